// round 16
// baseline (speedup 1.0000x reference)
#include <cuda_runtime.h>
#include <cuda_bf16.h>
#include <cuda_fp16.h>
#include <cstddef>
#include <cstdint>

// Problem constants
#define BATCH 2
#define T_LEN 2048
#define EMB   1024
#define NH    16
#define HD    64
#define BT    (BATCH * T_LEN)          // 4096

// ---------------- persistent scratch ----------------
__device__ __half g_xd16[(size_t)BT * EMB];   // down-proj output fp16
__device__ __half g_x16 [(size_t)BT * EMB];   // x as fp16
__device__ __half g_wd16[(size_t)EMB * EMB];  // W_down fp16
__device__ __half g_wu16[(size_t)EMB * EMB];  // W_unify fp16
__device__ __half g_wq16[(size_t)NH * HD * HD];  // toqueries fp16
__device__ __half g_wk16[(size_t)NH * HD * HD];  // tokeys fp16
__device__ __half g_wv16[(size_t)NH * HD * HD];  // tovalues fp16
__device__ __half g_ao16[(size_t)BT * EMB];   // attention out fp16
__device__ __half g_q  [(size_t)BT * EMB];    // q pre-scaled by s^-.25 * log2(e)
__device__ __half g_k  [(size_t)BT * EMB];
__device__ __half g_v  [(size_t)BT * EMB];

// ---------------- helpers ----------------
__device__ __forceinline__ uint32_t smem_u32(const void* p) {
    uint32_t a;
    asm("{ .reg .u64 t; cvta.to.shared.u64 t, %1; cvt.u32.u64 %0, t; }"
        : "=r"(a) : "l"(p));
    return a;
}
__device__ __forceinline__ void ldsm_x4(uint32_t* d, const void* p) {
    uint32_t a = smem_u32(p);
    asm volatile("ldmatrix.sync.aligned.m8n8.x4.shared.b16 {%0,%1,%2,%3}, [%4];"
                 : "=r"(d[0]), "=r"(d[1]), "=r"(d[2]), "=r"(d[3]) : "r"(a));
}
__device__ __forceinline__ void ldsm_x4t(uint32_t* d, const void* p) {
    uint32_t a = smem_u32(p);
    asm volatile("ldmatrix.sync.aligned.m8n8.x4.trans.shared.b16 {%0,%1,%2,%3}, [%4];"
                 : "=r"(d[0]), "=r"(d[1]), "=r"(d[2]), "=r"(d[3]) : "r"(a));
}
__device__ __forceinline__ void ldsm_x2(uint32_t* d, const void* p) {
    uint32_t a = smem_u32(p);
    asm volatile("ldmatrix.sync.aligned.m8n8.x2.shared.b16 {%0,%1}, [%2];"
                 : "=r"(d[0]), "=r"(d[1]) : "r"(a));
}
__device__ __forceinline__ void mma16816h(float* c, const uint32_t* a,
                                          const uint32_t* b) {
    asm volatile(
        "mma.sync.aligned.m16n8k16.row.col.f32.f16.f16.f32 "
        "{%0,%1,%2,%3}, {%4,%5,%6,%7}, {%8,%9}, {%0,%1,%2,%3};"
        : "+f"(c[0]), "+f"(c[1]), "+f"(c[2]), "+f"(c[3])
        : "r"(a[0]), "r"(a[1]), "r"(a[2]), "r"(a[3]), "r"(b[0]), "r"(b[1]));
}
__device__ __forceinline__ uint32_t hpack(float x, float y) {
    __half2 t = __floats2half2_rn(x, y);
    return *(uint32_t*)&t;
}
// half2 exp2: packs (lo,hi) fp32 -> f16x2, then MUFU ex2.f16x2
__device__ __forceinline__ uint32_t ex2h2(float lo, float hi) {
    uint32_t r;
    asm("{\n\t.reg .b32 t;\n\t"
        "cvt.rn.f16x2.f32 t, %2, %1;\n\t"
        "ex2.approx.f16x2 %0, t;\n\t}"
        : "=r"(r) : "f"(lo), "f"(hi));
    return r;
}
__device__ __forceinline__ void cp_async16(uint32_t dst, const void* src) {
    asm volatile("cp.async.cg.shared.global [%0], [%1], 16;"
                 :: "r"(dst), "l"(src));
}
#define CP_COMMIT() asm volatile("cp.async.commit_group;" ::: "memory")
#define CP_WAIT(N)  asm volatile("cp.async.wait_group %0;" :: "n"(N) : "memory")

// ---------------------------------------------------------------------------
// Fused convert kernel: six fp32->fp16 conversions in one launch.
// ---------------------------------------------------------------------------
__global__ __launch_bounds__(256)
void convert6_kernel(const float* __restrict__ s0, __half* __restrict__ d0, int n0,
                     const float* __restrict__ s1, __half* __restrict__ d1, int n1,
                     const float* __restrict__ s2, __half* __restrict__ d2, int n2,
                     const float* __restrict__ s3, __half* __restrict__ d3, int n3,
                     const float* __restrict__ s4, __half* __restrict__ d4, int n4,
                     const float* __restrict__ s5, __half* __restrict__ d5, int n5) {
    int i = blockIdx.x * 256 + threadIdx.x;
    const float* s; __half* d;
    if (i < n0) { s = s0; d = d0; }
    else if ((i -= n0) < n1) { s = s1; d = d1; }
    else if ((i -= n1) < n2) { s = s2; d = d2; }
    else if ((i -= n2) < n3) { s = s3; d = d3; }
    else if ((i -= n3) < n4) { s = s4; d = d4; }
    else if ((i -= n4) < n5) { s = s5; d = d5; }
    else return;
    float4 v = ((const float4*)s)[i];
    ((uint2*)d)[i] = make_uint2(hpack(v.x, v.y), hpack(v.z, v.w));
}

// ---------------------------------------------------------------------------
// fp16 GEMM: 128x128 CTA tile, 4 warps with 64x64 warp tiles (high MMA:ldsm),
// BK=64 stages, 3-stage cp.async ring, 128 threads, 2 CTAs/SM.
// Output: fp32 (+bias) if Cf != nullptr, else fp16 to Ch.
// ---------------------------------------------------------------------------
#define AST_H (128 * 72)               // 9216 halves per A stage
#define BST_H (64 * 136)               // 8704 halves per B stage
#define STG_H (AST_H + BST_H)          // 17920 halves = 35840 B per stage
#define HG_SMEM (3 * STG_H * 2)        // 107520 B

__device__ __forceinline__ void hg_load_stage(
    uint32_t sbase, const __half* A, const __half* B,
    size_t row0, int col0, int k0, int tid) {
    #pragma unroll
    for (int rep = 0; rep < 8; rep++) {
        int c = tid + rep * 128;
        int r = c >> 3, c8 = (c & 7) << 3;
        cp_async16(sbase + (uint32_t)(r * 72 + c8) * 2,
                   A + (row0 + r) * EMB + k0 + c8);
    }
    #pragma unroll
    for (int rep = 0; rep < 8; rep++) {
        int c = tid + rep * 128;
        int r = c >> 4, c8 = (c & 15) << 3;
        cp_async16(sbase + (uint32_t)(AST_H + r * 136 + c8) * 2,
                   B + (size_t)(k0 + r) * EMB + col0 + c8);
    }
}

__global__ __launch_bounds__(128, 2)
void hgemm_kernel(const __half* __restrict__ A,
                  const __half* __restrict__ B,
                  const float* __restrict__ bias,
                  float* __restrict__ Cf,
                  __half* __restrict__ Ch) {
    extern __shared__ __half hsm[];
    const uint32_t smem_base = smem_u32(hsm);

    const int tid  = threadIdx.x;
    const int lane = tid & 31;
    const int wid  = tid >> 5;        // 0..3
    const int g    = lane >> 2;
    const int tig  = lane & 3;
    const int wm   = (wid & 1) * 64;
    const int wn   = (wid >> 1) * 64;
    const size_t row0 = (size_t)blockIdx.y * 128;
    const int col0 = blockIdx.x * 128;

    float c[4][8][4] = {};

    const int aq  = lane >> 3;
    const int ar  = lane & 7;
    const int arow_off = (aq & 1) * 8 + ar;
    const int acol_off = (aq >> 1) * 8;
    const int brow_off = ((lane >> 3) & 1) * 8 + ar;
    const int bcol_sel = (lane >> 4);   // 0 or 1

    hg_load_stage(smem_base,             A, B, row0, col0, 0,  tid);
    CP_COMMIT();
    hg_load_stage(smem_base + STG_H * 2, A, B, row0, col0, 64, tid);
    CP_COMMIT();

    int s_cur = 0, s_nxt = 2;
    for (int i = 0; i < 16; i++) {
        if (i < 15) { CP_WAIT(1); } else { CP_WAIT(0); }
        __syncthreads();

        if (i + 2 < 16) {
            hg_load_stage(smem_base + s_nxt * (STG_H * 2),
                          A, B, row0, col0, (i + 2) * 64, tid);
            CP_COMMIT();
        }

        const __half* buf = hsm + s_cur * STG_H;
        const __half* Ash = buf;
        const __half* Bsh = buf + AST_H;

        #pragma unroll
        for (int ks = 0; ks < 4; ks++) {
            const int kc = ks * 16;
            uint32_t ah[4][4], bb[4][4];
            #pragma unroll
            for (int fm = 0; fm < 4; fm++) {
                const int r = wm + fm * 16 + arow_off;
                ldsm_x4(ah[fm], &Ash[r * 72 + kc + acol_off]);
            }
            #pragma unroll
            for (int fp = 0; fp < 4; fp++) {
                const int kr = kc + brow_off;
                const int cb = wn + fp * 16 + bcol_sel * 8;
                ldsm_x4t(bb[fp], &Bsh[kr * 136 + cb]);
            }
            #pragma unroll
            for (int fm = 0; fm < 4; fm++)
                #pragma unroll
                for (int fn = 0; fn < 8; fn++)
                    mma16816h(c[fm][fn], ah[fm], bb[fn >> 1] + (fn & 1) * 2);
        }
        s_cur = (s_cur == 2) ? 0 : s_cur + 1;
        s_nxt = (s_nxt == 2) ? 0 : s_nxt + 1;
    }

    if (Cf) {
        #pragma unroll
        for (int fm = 0; fm < 4; fm++) {
            #pragma unroll
            for (int fn = 0; fn < 8; fn++) {
                size_t rr = row0 + wm + fm * 16 + g;
                int cc = col0 + wn + fn * 8 + tig * 2;
                float b0 = 0.f, b1 = 0.f;
                if (bias) { b0 = bias[cc]; b1 = bias[cc + 1]; }
                *(float2*)&Cf[rr * EMB + cc] =
                    make_float2(c[fm][fn][0] + b0, c[fm][fn][1] + b1);
                *(float2*)&Cf[(rr + 8) * EMB + cc] =
                    make_float2(c[fm][fn][2] + b0, c[fm][fn][3] + b1);
            }
        }
    } else {
        #pragma unroll
        for (int fm = 0; fm < 4; fm++) {
            #pragma unroll
            for (int fn = 0; fn < 8; fn++) {
                size_t rr = row0 + wm + fm * 16 + g;
                int cc = col0 + wn + fn * 8 + tig * 2;
                *(uint32_t*)&Ch[rr * EMB + cc] = hpack(c[fm][fn][0], c[fm][fn][1]);
                *(uint32_t*)&Ch[(rr + 8) * EMB + cc] = hpack(c[fm][fn][2], c[fm][fn][3]);
            }
        }
    }
}

// ---------------------------------------------------------------------------
// QKV projection via fp16 mma.sync; reads fp16 xd and fp16 weights directly.
// q pre-scaled by s^-.25 * log2(e) so flash scores arrive in log2 units.
// ---------------------------------------------------------------------------
__global__ __launch_bounds__(256)
void qkv_mma_kernel(const __half* __restrict__ xd,
                    const __half* __restrict__ wq,
                    const __half* __restrict__ wk,
                    const __half* __restrict__ wv,
                    __half* __restrict__ qh,
                    __half* __restrict__ kh,
                    __half* __restrict__ vh) {
    __shared__ __half sX[128][72];
    __shared__ __half sW[3][64][72];

    const int bh = blockIdx.x;
    const int b = bh / NH, h = bh % NH;
    const int t0 = blockIdx.y * 128;

    const int tid  = threadIdx.x;
    const int lane = tid & 31;
    const int wid  = tid >> 5;
    const int g    = lane >> 2;
    const int tig  = lane & 3;
    const int wq_r = wid * 16;

    const int aq  = lane >> 3;
    const int ar  = lane & 7;
    const int arow_off = (aq & 1) * 8 + ar;
    const int acol_off = (aq >> 1) * 8;
    const int bq8 = ((lane >> 3) & 1) * 8;

    // copy fp16 xd tile (128x64) straight into smem
    #pragma unroll
    for (int rep = 0; rep < 4; rep++) {
        int f = tid + rep * 256;
        int r = f >> 3, c8 = (f & 7) << 3;
        *(uint4*)&sX[r][c8] =
            *(const uint4*)&xd[((size_t)(b * T_LEN) + t0 + r) * EMB + h * HD + c8];
    }
    // copy fp16 weights (64x64 each) straight into smem
    const __half* Ws[3] = {wq, wk, wv};
    #pragma unroll
    for (int z = 0; z < 3; z++) {
        const __half* W = Ws[z] + (size_t)h * HD * HD;
        #pragma unroll
        for (int rep = 0; rep < 2; rep++) {
            int f = tid + rep * 256;
            int r = f >> 3, c8 = (f & 7) << 3;
            *(uint4*)&sW[z][r][c8] = *(const uint4*)&W[r * HD + c8];
        }
    }
    __syncthreads();

    uint32_t af[4][4];
    #pragma unroll
    for (int ks = 0; ks < 4; ks++)
        ldsm_x4(af[ks], &sX[wq_r + arow_off][ks * 16 + acol_off]);

    __half* outs[3] = {qh, kh, vh};
    const float SC = 0.35355339059327373f;                 // 64^-0.25
    const float L2E = 1.4426950408889634f;
    #pragma unroll
    for (int z = 0; z < 3; z++) {
        float c[8][4] = {};
        #pragma unroll
        for (int nf = 0; nf < 8; nf++) {
            #pragma unroll
            for (int ks = 0; ks < 4; ks++) {
                uint32_t bw[2];
                ldsm_x2(bw, &sW[z][nf * 8 + ar][ks * 16 + bq8]);
                mma16816h(c[nf], af[ks], bw);
            }
        }
        const float scale = (z == 0) ? SC * L2E : ((z == 1) ? SC : 1.0f);
        __half* out = outs[z];
        int tr0 = t0 + wq_r + g;
        #pragma unroll
        for (int nf = 0; nf < 8; nf++) {
            int cc = nf * 8 + tig * 2;
            *(uint32_t*)&out[((size_t)bh * T_LEN + tr0) * HD + cc] =
                hpack(c[nf][0] * scale, c[nf][1] * scale);
            *(uint32_t*)&out[((size_t)bh * T_LEN + tr0 + 8) * HD + cc] =
                hpack(c[nf][2] * scale, c[nf][3] * scale);
        }
    }
}

// ---------------------------------------------------------------------------
// Flash attention (R12/R15 best-measured body): 256-query CTA tile
// (8 warps x 32 query rows), KV tile 128, fixed-max ex2 softmax.
// NOW with 3-stage cp.async KV ring (2-iteration prefetch slack).
// ---------------------------------------------------------------------------
#define QT    256
#define KVST (128 * 72)                              // halves per KV stage
#define FLASH_SMEM ((QT * 72 + 6 * KVST) * 2)        // 147456 B

__global__ __launch_bounds__(256, 1)
void flash_mma_kernel(const __half* __restrict__ Qg,
                      const __half* __restrict__ Kg,
                      const __half* __restrict__ Vg,
                      __half* __restrict__ Oa) {
    extern __shared__ __half fsm[];
    __half* sQ  = fsm;                      // [256][72]
    __half* sKb = fsm + QT * 72;            // 3 stages [128][72]
    __half* sVb = sKb + 3 * KVST;
    const uint32_t sK_u32 = smem_u32(sKb);
    const uint32_t sV_u32 = smem_u32(sVb);

    const int bh = blockIdx.x;
    const int q0 = blockIdx.y * QT;
    const int b = bh / NH, h = bh % NH;

    const __half* Qb = Qg + (size_t)bh * T_LEN * HD;
    const __half* Kb = Kg + (size_t)bh * T_LEN * HD;
    const __half* Vb = Vg + (size_t)bh * T_LEN * HD;

    const int tid  = threadIdx.x;
    const int lane = tid & 31;
    const int wid  = tid >> 5;
    const int g    = lane >> 2;
    const int tig  = lane & 3;
    const int wq   = wid * 32;           // warp's 32-query base

    const int aq  = lane >> 3;
    const int ar  = lane & 7;
    const int arow_off = (aq & 1) * 8 + ar;
    const int acol_off = (aq >> 1) * 8;
    const int kcol4 = aq * 8;
    const int vrow_off = ((lane >> 3) & 1) * 8 + ar;
    const int vcol_sel = (lane >> 4);

    const int kvr = tid >> 3;            // 0..31, reps add +32
    const int kvc8 = (tid & 7) << 3;

    // prologue: KV stages 0 and 1 + Q (256 rows)
    #pragma unroll
    for (int rep = 0; rep < 4; rep++) {
        int r = kvr + rep * 32;
        uint32_t off = (uint32_t)(r * 72 + kvc8) * 2;
        cp_async16(sK_u32 + off, Kb + (size_t)r * HD + kvc8);
        cp_async16(sV_u32 + off, Vb + (size_t)r * HD + kvc8);
    }
    CP_COMMIT();
    #pragma unroll
    for (int rep = 0; rep < 4; rep++) {
        int r = kvr + rep * 32;
        uint32_t off = (uint32_t)(KVST + r * 72 + kvc8) * 2;
        cp_async16(sK_u32 + off, Kb + (size_t)(128 + r) * HD + kvc8);
        cp_async16(sV_u32 + off, Vb + (size_t)(128 + r) * HD + kvc8);
    }
    CP_COMMIT();

    #pragma unroll
    for (int rep = 0; rep < 8; rep++) {
        int f = tid + rep * 256;
        int r = f >> 3, c8 = (f & 7) << 3;
        *(uint4*)&sQ[r * 72 + c8] = *(const uint4*)&Qb[(size_t)(q0 + r) * HD + c8];
    }
    __syncthreads();

    // Q fragments for both query groups, resident all kernel
    uint32_t qf[2][4][4];
    #pragma unroll
    for (int qg = 0; qg < 2; qg++)
        #pragma unroll
        for (int ks = 0; ks < 4; ks++)
            ldsm_x4(qf[qg][ks], &sQ[(wq + qg * 16 + arow_off) * 72 + ks * 16 + acol_off]);

    const uint32_t ONES2 = 0x3C003C00u;
    uint32_t onesb[2] = {ONES2, ONES2};

    float lacc[2][4] = {};
    float o[2][8][4] = {};

    int s_cur = 0, s_nxt = 2;
    for (int i = 0; i < 16; i++) {
        if (i < 15) { CP_WAIT(1); } else { CP_WAIT(0); }
        __syncthreads();

        if (i + 2 < 16) {
            const int k0n = (i + 2) * 128;
            const uint32_t sb = (uint32_t)s_nxt * (KVST * 2);
            #pragma unroll
            for (int rep = 0; rep < 4; rep++) {
                int r = kvr + rep * 32;
                uint32_t off = sb + (uint32_t)(r * 72 + kvc8) * 2;
                cp_async16(sK_u32 + off, Kb + (size_t)(k0n + r) * HD + kvc8);
                cp_async16(sV_u32 + off, Vb + (size_t)(k0n + r) * HD + kvc8);
            }
            CP_COMMIT();
        }

        const __half* sK = sKb + s_cur * KVST;
        const __half* sV = sVb + s_cur * KVST;

        // ---- per 16-key block: K-frags, S/P for both q-groups, PV ----
        #pragma unroll
        for (int kb = 0; kb < 8; kb++) {
            uint32_t bk[8];
            ldsm_x4(bk,     &sK[(kb * 16 + ar) * 72 + kcol4]);
            ldsm_x4(bk + 4, &sK[(kb * 16 + 8 + ar) * 72 + kcol4]);

            uint32_t af[2][4];
            #pragma unroll
            for (int qg = 0; qg < 2; qg++) {
                float s0[4] = {}, s1[4] = {};
                #pragma unroll
                for (int ks = 0; ks < 2; ks++) {
                    mma16816h(s0, qf[qg][ks], bk + ks * 2);
                    mma16816h(s1, qf[qg][ks], bk + 4 + ks * 2);
                }
                uint32_t bk2[8];
                ldsm_x4(bk2,     &sK[(kb * 16 + ar) * 72 + 32 + kcol4]);
                ldsm_x4(bk2 + 4, &sK[(kb * 16 + 8 + ar) * 72 + 32 + kcol4]);
                #pragma unroll
                for (int ks = 0; ks < 2; ks++) {
                    mma16816h(s0, qf[qg][2 + ks], bk2 + ks * 2);
                    mma16816h(s1, qf[qg][2 + ks], bk2 + 4 + ks * 2);
                }
                af[qg][0] = ex2h2(s0[0], s0[1]);
                af[qg][1] = ex2h2(s0[2], s0[3]);
                af[qg][2] = ex2h2(s1[0], s1[1]);
                af[qg][3] = ex2h2(s1[2], s1[3]);
                mma16816h(lacc[qg], af[qg], onesb);
            }

            // ---- V-frags once, PV for both q-groups ----
            #pragma unroll
            for (int nf = 0; nf < 8; nf += 2) {
                uint32_t bv[4];
                ldsm_x4t(bv, &sV[(kb * 16 + vrow_off) * 72 + (nf + vcol_sel) * 8]);
                #pragma unroll
                for (int qg = 0; qg < 2; qg++) {
                    mma16816h(o[qg][nf], af[qg], bv);
                    mma16816h(o[qg][nf + 1], af[qg], bv + 2);
                }
            }
        }
        s_cur = (s_cur == 2) ? 0 : s_cur + 1;
        s_nxt = (s_nxt == 2) ? 0 : s_nxt + 1;
    }

    // ---- epilogue: normalize, write fp16 ao at [b, q, h, s] ----
    #pragma unroll
    for (int qg = 0; qg < 2; qg++) {
        float inv0 = 1.0f / lacc[qg][0], inv1 = 1.0f / lacc[qg][2];
        int qr0 = q0 + wq + qg * 16 + g;
        int qr1 = qr0 + 8;
        #pragma unroll
        for (int nf = 0; nf < 8; nf++) {
            int cc = nf * 8 + tig * 2;
            size_t i0 = ((size_t)(b * T_LEN + qr0) * NH + h) * HD + cc;
            size_t i1 = ((size_t)(b * T_LEN + qr1) * NH + h) * HD + cc;
            *(uint32_t*)&Oa[i0] = hpack(o[qg][nf][0] * inv0, o[qg][nf][1] * inv0);
            *(uint32_t*)&Oa[i1] = hpack(o[qg][nf][2] * inv1, o[qg][nf][3] * inv1);
        }
    }
}

// ---------------------------------------------------------------------------
extern "C" void kernel_launch(void* const* d_in, const int* in_sizes, int n_in,
                              void* d_out, int out_size) {
    const float* x        = (const float*)d_in[0];
    const float* W_down   = (const float*)d_in[1];
    const float* tokeys   = (const float*)d_in[2];
    const float* toquery  = (const float*)d_in[3];
    const float* tovalues = (const float*)d_in[4];
    const float* W_unify  = (const float*)d_in[5];
    const float* b_unify  = (const float*)d_in[6];
    float* out = (float*)d_out;

    __half *p_xd16, *p_x16, *p_wd16, *p_wu16, *p_wq16, *p_wk16, *p_wv16;
    __half *p_ao16, *p_q, *p_k, *p_v;
    cudaGetSymbolAddress((void**)&p_xd16, g_xd16);
    cudaGetSymbolAddress((void**)&p_x16,  g_x16);
    cudaGetSymbolAddress((void**)&p_wd16, g_wd16);
    cudaGetSymbolAddress((void**)&p_wu16, g_wu16);
    cudaGetSymbolAddress((void**)&p_wq16, g_wq16);
    cudaGetSymbolAddress((void**)&p_wk16, g_wk16);
    cudaGetSymbolAddress((void**)&p_wv16, g_wv16);
    cudaGetSymbolAddress((void**)&p_ao16, g_ao16);
    cudaGetSymbolAddress((void**)&p_q,    g_q);
    cudaGetSymbolAddress((void**)&p_k,    g_k);
    cudaGetSymbolAddress((void**)&p_v,    g_v);

    cudaFuncSetAttribute(hgemm_kernel,
                         cudaFuncAttributeMaxDynamicSharedMemorySize, HG_SMEM);
    cudaFuncSetAttribute(flash_mma_kernel,
                         cudaFuncAttributeMaxDynamicSharedMemorySize, FLASH_SMEM);

    // 0) fused fp32->fp16 converts: x, W_down, W_unify, toqueries, tokeys, tovalues
    const int n0 = BT * EMB / 4, n1 = EMB * EMB / 4, n2 = EMB * EMB / 4;
    const int nw = NH * HD * HD / 4;
    convert6_kernel<<<(n0 + n1 + n2 + 3 * nw + 255) / 256, 256>>>(
        x, p_x16, n0, W_down, p_wd16, n1, W_unify, p_wu16, n2,
        toquery, p_wq16, nw, tokeys, p_wk16, nw, tovalues, p_wv16, nw);

    // 1) xd = x @ W_down   (fp16 HMMA, 64x64 warp tiles, fp16 output)
    hgemm_kernel<<<dim3(EMB / 128, BT / 128), 128, HG_SMEM>>>(
        p_x16, p_wd16, nullptr, nullptr, p_xd16);

    // 2) q,k,v per-head projections (all-fp16; q pre-scaled by log2e)
    qkv_mma_kernel<<<dim3(BATCH * NH, T_LEN / 128), 256>>>(
        p_xd16, p_wq16, p_wk16, p_wv16, p_q, p_k, p_v);

    // 3) flash attention (3-stage KV ring) -> fp16 ao
    flash_mma_kernel<<<dim3(BATCH * NH, T_LEN / QT), 256, FLASH_SMEM>>>(
        p_q, p_k, p_v, p_ao16);

    // 4) out = ao @ W_unify + b_unify   (fp16 HMMA, 64x64 warp tiles, fp32 out)
    hgemm_kernel<<<dim3(EMB / 128, BT / 128), 128, HG_SMEM>>>(
        p_ao16, p_wu16, b_unify, out, nullptr);
}

// round 17
// speedup vs baseline: 1.0183x; 1.0183x over previous
#include <cuda_runtime.h>
#include <cuda_bf16.h>
#include <cuda_fp16.h>
#include <cstddef>
#include <cstdint>

// Problem constants
#define BATCH 2
#define T_LEN 2048
#define EMB   1024
#define NH    16
#define HD    64
#define BT    (BATCH * T_LEN)          // 4096

// ---------------- persistent scratch ----------------
__device__ __half g_xd16[(size_t)BT * EMB];   // down-proj output fp16
__device__ __half g_x16 [(size_t)BT * EMB];   // x as fp16
__device__ __half g_wd16[(size_t)EMB * EMB];  // W_down fp16
__device__ __half g_wu16[(size_t)EMB * EMB];  // W_unify fp16
__device__ __half g_wq16[(size_t)NH * HD * HD];  // toqueries fp16
__device__ __half g_wk16[(size_t)NH * HD * HD];  // tokeys fp16
__device__ __half g_wv16[(size_t)NH * HD * HD];  // tovalues fp16
__device__ __half g_ao16[(size_t)BT * EMB];   // attention out fp16
__device__ __half g_q  [(size_t)BT * EMB];    // q pre-scaled by s^-.25 * log2(e)
__device__ __half g_k  [(size_t)BT * EMB];
__device__ __half g_v  [(size_t)BT * EMB];

// ---------------- helpers ----------------
__device__ __forceinline__ uint32_t smem_u32(const void* p) {
    uint32_t a;
    asm("{ .reg .u64 t; cvta.to.shared.u64 t, %1; cvt.u32.u64 %0, t; }"
        : "=r"(a) : "l"(p));
    return a;
}
__device__ __forceinline__ void ldsm_x4(uint32_t* d, const void* p) {
    uint32_t a = smem_u32(p);
    asm volatile("ldmatrix.sync.aligned.m8n8.x4.shared.b16 {%0,%1,%2,%3}, [%4];"
                 : "=r"(d[0]), "=r"(d[1]), "=r"(d[2]), "=r"(d[3]) : "r"(a));
}
__device__ __forceinline__ void ldsm_x4t(uint32_t* d, const void* p) {
    uint32_t a = smem_u32(p);
    asm volatile("ldmatrix.sync.aligned.m8n8.x4.trans.shared.b16 {%0,%1,%2,%3}, [%4];"
                 : "=r"(d[0]), "=r"(d[1]), "=r"(d[2]), "=r"(d[3]) : "r"(a));
}
__device__ __forceinline__ void ldsm_x2(uint32_t* d, const void* p) {
    uint32_t a = smem_u32(p);
    asm volatile("ldmatrix.sync.aligned.m8n8.x2.shared.b16 {%0,%1}, [%2];"
                 : "=r"(d[0]), "=r"(d[1]) : "r"(a));
}
__device__ __forceinline__ void mma16816h(float* c, const uint32_t* a,
                                          const uint32_t* b) {
    asm volatile(
        "mma.sync.aligned.m16n8k16.row.col.f32.f16.f16.f32 "
        "{%0,%1,%2,%3}, {%4,%5,%6,%7}, {%8,%9}, {%0,%1,%2,%3};"
        : "+f"(c[0]), "+f"(c[1]), "+f"(c[2]), "+f"(c[3])
        : "r"(a[0]), "r"(a[1]), "r"(a[2]), "r"(a[3]), "r"(b[0]), "r"(b[1]));
}
__device__ __forceinline__ uint32_t hpack(float x, float y) {
    __half2 t = __floats2half2_rn(x, y);
    return *(uint32_t*)&t;
}
// half2 exp2: packs (lo,hi) fp32 -> f16x2, then MUFU ex2.f16x2
__device__ __forceinline__ uint32_t ex2h2(float lo, float hi) {
    uint32_t r;
    asm("{\n\t.reg .b32 t;\n\t"
        "cvt.rn.f16x2.f32 t, %2, %1;\n\t"
        "ex2.approx.f16x2 %0, t;\n\t}"
        : "=r"(r) : "f"(lo), "f"(hi));
    return r;
}
__device__ __forceinline__ void cp_async16(uint32_t dst, const void* src) {
    asm volatile("cp.async.cg.shared.global [%0], [%1], 16;"
                 :: "r"(dst), "l"(src));
}
#define CP_COMMIT() asm volatile("cp.async.commit_group;" ::: "memory")
#define CP_WAIT(N)  asm volatile("cp.async.wait_group %0;" :: "n"(N) : "memory")

// ---------------------------------------------------------------------------
// Fused convert kernel: six fp32->fp16 conversions in one launch.
// ---------------------------------------------------------------------------
__global__ __launch_bounds__(256)
void convert6_kernel(const float* __restrict__ s0, __half* __restrict__ d0, int n0,
                     const float* __restrict__ s1, __half* __restrict__ d1, int n1,
                     const float* __restrict__ s2, __half* __restrict__ d2, int n2,
                     const float* __restrict__ s3, __half* __restrict__ d3, int n3,
                     const float* __restrict__ s4, __half* __restrict__ d4, int n4,
                     const float* __restrict__ s5, __half* __restrict__ d5, int n5) {
    int i = blockIdx.x * 256 + threadIdx.x;
    const float* s; __half* d;
    if (i < n0) { s = s0; d = d0; }
    else if ((i -= n0) < n1) { s = s1; d = d1; }
    else if ((i -= n1) < n2) { s = s2; d = d2; }
    else if ((i -= n2) < n3) { s = s3; d = d3; }
    else if ((i -= n3) < n4) { s = s4; d = d4; }
    else if ((i -= n4) < n5) { s = s5; d = d5; }
    else return;
    float4 v = ((const float4*)s)[i];
    ((uint2*)d)[i] = make_uint2(hpack(v.x, v.y), hpack(v.z, v.w));
}

// ---------------------------------------------------------------------------
// fp16 GEMM: 128x128 CTA tile, 4 warps with 64x64 warp tiles (high MMA:ldsm),
// BK=64 stages, 3-stage cp.async ring, 128 threads, 2 CTAs/SM.
// Output: fp32 (+bias) if Cf != nullptr, else fp16 to Ch.
// ---------------------------------------------------------------------------
#define AST_H (128 * 72)               // 9216 halves per A stage
#define BST_H (64 * 136)               // 8704 halves per B stage
#define STG_H (AST_H + BST_H)          // 17920 halves = 35840 B per stage
#define HG_SMEM (3 * STG_H * 2)        // 107520 B

__device__ __forceinline__ void hg_load_stage(
    uint32_t sbase, const __half* A, const __half* B,
    size_t row0, int col0, int k0, int tid) {
    #pragma unroll
    for (int rep = 0; rep < 8; rep++) {
        int c = tid + rep * 128;
        int r = c >> 3, c8 = (c & 7) << 3;
        cp_async16(sbase + (uint32_t)(r * 72 + c8) * 2,
                   A + (row0 + r) * EMB + k0 + c8);
    }
    #pragma unroll
    for (int rep = 0; rep < 8; rep++) {
        int c = tid + rep * 128;
        int r = c >> 4, c8 = (c & 15) << 3;
        cp_async16(sbase + (uint32_t)(AST_H + r * 136 + c8) * 2,
                   B + (size_t)(k0 + r) * EMB + col0 + c8);
    }
}

__global__ __launch_bounds__(128, 2)
void hgemm_kernel(const __half* __restrict__ A,
                  const __half* __restrict__ B,
                  const float* __restrict__ bias,
                  float* __restrict__ Cf,
                  __half* __restrict__ Ch) {
    extern __shared__ __half hsm[];
    const uint32_t smem_base = smem_u32(hsm);

    const int tid  = threadIdx.x;
    const int lane = tid & 31;
    const int wid  = tid >> 5;        // 0..3
    const int g    = lane >> 2;
    const int tig  = lane & 3;
    const int wm   = (wid & 1) * 64;
    const int wn   = (wid >> 1) * 64;
    const size_t row0 = (size_t)blockIdx.y * 128;
    const int col0 = blockIdx.x * 128;

    float c[4][8][4] = {};

    const int aq  = lane >> 3;
    const int ar  = lane & 7;
    const int arow_off = (aq & 1) * 8 + ar;
    const int acol_off = (aq >> 1) * 8;
    const int brow_off = ((lane >> 3) & 1) * 8 + ar;
    const int bcol_sel = (lane >> 4);   // 0 or 1

    hg_load_stage(smem_base,             A, B, row0, col0, 0,  tid);
    CP_COMMIT();
    hg_load_stage(smem_base + STG_H * 2, A, B, row0, col0, 64, tid);
    CP_COMMIT();

    int s_cur = 0, s_nxt = 2;
    for (int i = 0; i < 16; i++) {
        if (i < 15) { CP_WAIT(1); } else { CP_WAIT(0); }
        __syncthreads();

        if (i + 2 < 16) {
            hg_load_stage(smem_base + s_nxt * (STG_H * 2),
                          A, B, row0, col0, (i + 2) * 64, tid);
            CP_COMMIT();
        }

        const __half* buf = hsm + s_cur * STG_H;
        const __half* Ash = buf;
        const __half* Bsh = buf + AST_H;

        #pragma unroll
        for (int ks = 0; ks < 4; ks++) {
            const int kc = ks * 16;
            uint32_t ah[4][4], bb[4][4];
            #pragma unroll
            for (int fm = 0; fm < 4; fm++) {
                const int r = wm + fm * 16 + arow_off;
                ldsm_x4(ah[fm], &Ash[r * 72 + kc + acol_off]);
            }
            #pragma unroll
            for (int fp = 0; fp < 4; fp++) {
                const int kr = kc + brow_off;
                const int cb = wn + fp * 16 + bcol_sel * 8;
                ldsm_x4t(bb[fp], &Bsh[kr * 136 + cb]);
            }
            #pragma unroll
            for (int fm = 0; fm < 4; fm++)
                #pragma unroll
                for (int fn = 0; fn < 8; fn++)
                    mma16816h(c[fm][fn], ah[fm], bb[fn >> 1] + (fn & 1) * 2);
        }
        s_cur = (s_cur == 2) ? 0 : s_cur + 1;
        s_nxt = (s_nxt == 2) ? 0 : s_nxt + 1;
    }

    if (Cf) {
        #pragma unroll
        for (int fm = 0; fm < 4; fm++) {
            #pragma unroll
            for (int fn = 0; fn < 8; fn++) {
                size_t rr = row0 + wm + fm * 16 + g;
                int cc = col0 + wn + fn * 8 + tig * 2;
                float b0 = 0.f, b1 = 0.f;
                if (bias) { b0 = bias[cc]; b1 = bias[cc + 1]; }
                *(float2*)&Cf[rr * EMB + cc] =
                    make_float2(c[fm][fn][0] + b0, c[fm][fn][1] + b1);
                *(float2*)&Cf[(rr + 8) * EMB + cc] =
                    make_float2(c[fm][fn][2] + b0, c[fm][fn][3] + b1);
            }
        }
    } else {
        #pragma unroll
        for (int fm = 0; fm < 4; fm++) {
            #pragma unroll
            for (int fn = 0; fn < 8; fn++) {
                size_t rr = row0 + wm + fm * 16 + g;
                int cc = col0 + wn + fn * 8 + tig * 2;
                *(uint32_t*)&Ch[rr * EMB + cc] = hpack(c[fm][fn][0], c[fm][fn][1]);
                *(uint32_t*)&Ch[(rr + 8) * EMB + cc] = hpack(c[fm][fn][2], c[fm][fn][3]);
            }
        }
    }
}

// ---------------------------------------------------------------------------
// QKV projection via fp16 mma.sync; reads fp16 xd and fp16 weights directly.
// q pre-scaled by s^-.25 * log2(e) so flash scores arrive in log2 units.
// ---------------------------------------------------------------------------
__global__ __launch_bounds__(256)
void qkv_mma_kernel(const __half* __restrict__ xd,
                    const __half* __restrict__ wq,
                    const __half* __restrict__ wk,
                    const __half* __restrict__ wv,
                    __half* __restrict__ qh,
                    __half* __restrict__ kh,
                    __half* __restrict__ vh) {
    __shared__ __half sX[128][72];
    __shared__ __half sW[3][64][72];

    const int bh = blockIdx.x;
    const int b = bh / NH, h = bh % NH;
    const int t0 = blockIdx.y * 128;

    const int tid  = threadIdx.x;
    const int lane = tid & 31;
    const int wid  = tid >> 5;
    const int g    = lane >> 2;
    const int tig  = lane & 3;
    const int wq_r = wid * 16;

    const int aq  = lane >> 3;
    const int ar  = lane & 7;
    const int arow_off = (aq & 1) * 8 + ar;
    const int acol_off = (aq >> 1) * 8;
    const int bq8 = ((lane >> 3) & 1) * 8;

    // copy fp16 xd tile (128x64) straight into smem
    #pragma unroll
    for (int rep = 0; rep < 4; rep++) {
        int f = tid + rep * 256;
        int r = f >> 3, c8 = (f & 7) << 3;
        *(uint4*)&sX[r][c8] =
            *(const uint4*)&xd[((size_t)(b * T_LEN) + t0 + r) * EMB + h * HD + c8];
    }
    // copy fp16 weights (64x64 each) straight into smem
    const __half* Ws[3] = {wq, wk, wv};
    #pragma unroll
    for (int z = 0; z < 3; z++) {
        const __half* W = Ws[z] + (size_t)h * HD * HD;
        #pragma unroll
        for (int rep = 0; rep < 2; rep++) {
            int f = tid + rep * 256;
            int r = f >> 3, c8 = (f & 7) << 3;
            *(uint4*)&sW[z][r][c8] = *(const uint4*)&W[r * HD + c8];
        }
    }
    __syncthreads();

    uint32_t af[4][4];
    #pragma unroll
    for (int ks = 0; ks < 4; ks++)
        ldsm_x4(af[ks], &sX[wq_r + arow_off][ks * 16 + acol_off]);

    __half* outs[3] = {qh, kh, vh};
    const float SC = 0.35355339059327373f;                 // 64^-0.25
    const float L2E = 1.4426950408889634f;
    #pragma unroll
    for (int z = 0; z < 3; z++) {
        float c[8][4] = {};
        #pragma unroll
        for (int nf = 0; nf < 8; nf++) {
            #pragma unroll
            for (int ks = 0; ks < 4; ks++) {
                uint32_t bw[2];
                ldsm_x2(bw, &sW[z][nf * 8 + ar][ks * 16 + bq8]);
                mma16816h(c[nf], af[ks], bw);
            }
        }
        const float scale = (z == 0) ? SC * L2E : ((z == 1) ? SC : 1.0f);
        __half* out = outs[z];
        int tr0 = t0 + wq_r + g;
        #pragma unroll
        for (int nf = 0; nf < 8; nf++) {
            int cc = nf * 8 + tig * 2;
            *(uint32_t*)&out[((size_t)bh * T_LEN + tr0) * HD + cc] =
                hpack(c[nf][0] * scale, c[nf][1] * scale);
            *(uint32_t*)&out[((size_t)bh * T_LEN + tr0 + 8) * HD + cc] =
                hpack(c[nf][2] * scale, c[nf][3] * scale);
        }
    }
}

// ---------------------------------------------------------------------------
// Flash attention (R15 best-measured variant, byte-exact): 256-query CTA tile
// (8 warps x 32 query rows), KV tile 128, 2-stage cp.async, fixed-max ex2
// softmax. K/V fragments loaded per 16-key block, reused for both 16-row
// query groups.
// ---------------------------------------------------------------------------
#define QT    256
#define KVST (128 * 72)                              // halves per KV stage
#define FLASH_SMEM ((QT * 72 + 4 * KVST) * 2)        // 110592 B

__global__ __launch_bounds__(256, 1)
void flash_mma_kernel(const __half* __restrict__ Qg,
                      const __half* __restrict__ Kg,
                      const __half* __restrict__ Vg,
                      __half* __restrict__ Oa) {
    extern __shared__ __half fsm[];
    __half* sQ  = fsm;                      // [256][72]
    __half* sKb = fsm + QT * 72;            // 2 stages [128][72]
    __half* sVb = sKb + 2 * KVST;
    const uint32_t sK_u32 = smem_u32(sKb);
    const uint32_t sV_u32 = smem_u32(sVb);

    const int bh = blockIdx.x;
    const int q0 = blockIdx.y * QT;
    const int b = bh / NH, h = bh % NH;

    const __half* Qb = Qg + (size_t)bh * T_LEN * HD;
    const __half* Kb = Kg + (size_t)bh * T_LEN * HD;
    const __half* Vb = Vg + (size_t)bh * T_LEN * HD;

    const int tid  = threadIdx.x;
    const int lane = tid & 31;
    const int wid  = tid >> 5;
    const int g    = lane >> 2;
    const int tig  = lane & 3;
    const int wq   = wid * 32;           // warp's 32-query base

    const int aq  = lane >> 3;
    const int ar  = lane & 7;
    const int arow_off = (aq & 1) * 8 + ar;
    const int acol_off = (aq >> 1) * 8;
    const int kcol4 = aq * 8;
    const int vrow_off = ((lane >> 3) & 1) * 8 + ar;
    const int vcol_sel = (lane >> 4);

    const int kvr = tid >> 3;            // 0..31, reps add +32
    const int kvc8 = (tid & 7) << 3;

    // prologue: KV stage 0 (128 rows each) + Q (256 rows)
    #pragma unroll
    for (int rep = 0; rep < 4; rep++) {
        int r = kvr + rep * 32;
        uint32_t off = (uint32_t)(r * 72 + kvc8) * 2;
        cp_async16(sK_u32 + off, Kb + (size_t)r * HD + kvc8);
        cp_async16(sV_u32 + off, Vb + (size_t)r * HD + kvc8);
    }
    CP_COMMIT();

    #pragma unroll
    for (int rep = 0; rep < 8; rep++) {
        int f = tid + rep * 256;
        int r = f >> 3, c8 = (f & 7) << 3;
        *(uint4*)&sQ[r * 72 + c8] = *(const uint4*)&Qb[(size_t)(q0 + r) * HD + c8];
    }
    __syncthreads();

    // Q fragments for both query groups, resident all kernel
    uint32_t qf[2][4][4];
    #pragma unroll
    for (int qg = 0; qg < 2; qg++)
        #pragma unroll
        for (int ks = 0; ks < 4; ks++)
            ldsm_x4(qf[qg][ks], &sQ[(wq + qg * 16 + arow_off) * 72 + ks * 16 + acol_off]);

    const uint32_t ONES2 = 0x3C003C00u;
    uint32_t onesb[2] = {ONES2, ONES2};

    float lacc[2][4] = {};
    float o[2][8][4] = {};

    for (int i = 0; i < 16; i++) {
        CP_WAIT(0);
        __syncthreads();

        if (i + 1 < 16) {
            const int k0n = (i + 1) * 128;
            const uint32_t sb = ((i + 1) & 1) * (KVST * 2);
            #pragma unroll
            for (int rep = 0; rep < 4; rep++) {
                int r = kvr + rep * 32;
                uint32_t off = sb + (uint32_t)(r * 72 + kvc8) * 2;
                cp_async16(sK_u32 + off, Kb + (size_t)(k0n + r) * HD + kvc8);
                cp_async16(sV_u32 + off, Vb + (size_t)(k0n + r) * HD + kvc8);
            }
            CP_COMMIT();
        }

        const __half* sK = sKb + (i & 1) * KVST;
        const __half* sV = sVb + (i & 1) * KVST;

        // ---- per 16-key block: K-frags, S/P for both q-groups, PV ----
        #pragma unroll
        for (int kb = 0; kb < 8; kb++) {
            uint32_t bk[8];
            ldsm_x4(bk,     &sK[(kb * 16 + ar) * 72 + kcol4]);
            ldsm_x4(bk + 4, &sK[(kb * 16 + 8 + ar) * 72 + kcol4]);

            uint32_t af[2][4];
            #pragma unroll
            for (int qg = 0; qg < 2; qg++) {
                float s0[4] = {}, s1[4] = {};
                #pragma unroll
                for (int ks = 0; ks < 2; ks++) {
                    mma16816h(s0, qf[qg][ks], bk + ks * 2);
                    mma16816h(s1, qf[qg][ks], bk + 4 + ks * 2);
                }
                uint32_t bk2[8];
                ldsm_x4(bk2,     &sK[(kb * 16 + ar) * 72 + 32 + kcol4]);
                ldsm_x4(bk2 + 4, &sK[(kb * 16 + 8 + ar) * 72 + 32 + kcol4]);
                #pragma unroll
                for (int ks = 0; ks < 2; ks++) {
                    mma16816h(s0, qf[qg][2 + ks], bk2 + ks * 2);
                    mma16816h(s1, qf[qg][2 + ks], bk2 + 4 + ks * 2);
                }
                af[qg][0] = ex2h2(s0[0], s0[1]);
                af[qg][1] = ex2h2(s0[2], s0[3]);
                af[qg][2] = ex2h2(s1[0], s1[1]);
                af[qg][3] = ex2h2(s1[2], s1[3]);
                mma16816h(lacc[qg], af[qg], onesb);
            }

            // ---- V-frags once, PV for both q-groups ----
            #pragma unroll
            for (int nf = 0; nf < 8; nf += 2) {
                uint32_t bv[4];
                ldsm_x4t(bv, &sV[(kb * 16 + vrow_off) * 72 + (nf + vcol_sel) * 8]);
                #pragma unroll
                for (int qg = 0; qg < 2; qg++) {
                    mma16816h(o[qg][nf], af[qg], bv);
                    mma16816h(o[qg][nf + 1], af[qg], bv + 2);
                }
            }
        }
    }

    // ---- epilogue: normalize, write fp16 ao at [b, q, h, s] ----
    #pragma unroll
    for (int qg = 0; qg < 2; qg++) {
        float inv0 = 1.0f / lacc[qg][0], inv1 = 1.0f / lacc[qg][2];
        int qr0 = q0 + wq + qg * 16 + g;
        int qr1 = qr0 + 8;
        #pragma unroll
        for (int nf = 0; nf < 8; nf++) {
            int cc = nf * 8 + tig * 2;
            size_t i0 = ((size_t)(b * T_LEN + qr0) * NH + h) * HD + cc;
            size_t i1 = ((size_t)(b * T_LEN + qr1) * NH + h) * HD + cc;
            *(uint32_t*)&Oa[i0] = hpack(o[qg][nf][0] * inv0, o[qg][nf][1] * inv0);
            *(uint32_t*)&Oa[i1] = hpack(o[qg][nf][2] * inv1, o[qg][nf][3] * inv1);
        }
    }
}

// ---------------------------------------------------------------------------
extern "C" void kernel_launch(void* const* d_in, const int* in_sizes, int n_in,
                              void* d_out, int out_size) {
    const float* x        = (const float*)d_in[0];
    const float* W_down   = (const float*)d_in[1];
    const float* tokeys   = (const float*)d_in[2];
    const float* toquery  = (const float*)d_in[3];
    const float* tovalues = (const float*)d_in[4];
    const float* W_unify  = (const float*)d_in[5];
    const float* b_unify  = (const float*)d_in[6];
    float* out = (float*)d_out;

    __half *p_xd16, *p_x16, *p_wd16, *p_wu16, *p_wq16, *p_wk16, *p_wv16;
    __half *p_ao16, *p_q, *p_k, *p_v;
    cudaGetSymbolAddress((void**)&p_xd16, g_xd16);
    cudaGetSymbolAddress((void**)&p_x16,  g_x16);
    cudaGetSymbolAddress((void**)&p_wd16, g_wd16);
    cudaGetSymbolAddress((void**)&p_wu16, g_wu16);
    cudaGetSymbolAddress((void**)&p_wq16, g_wq16);
    cudaGetSymbolAddress((void**)&p_wk16, g_wk16);
    cudaGetSymbolAddress((void**)&p_wv16, g_wv16);
    cudaGetSymbolAddress((void**)&p_ao16, g_ao16);
    cudaGetSymbolAddress((void**)&p_q,    g_q);
    cudaGetSymbolAddress((void**)&p_k,    g_k);
    cudaGetSymbolAddress((void**)&p_v,    g_v);

    cudaFuncSetAttribute(hgemm_kernel,
                         cudaFuncAttributeMaxDynamicSharedMemorySize, HG_SMEM);
    cudaFuncSetAttribute(flash_mma_kernel,
                         cudaFuncAttributeMaxDynamicSharedMemorySize, FLASH_SMEM);

    // 0) fused fp32->fp16 converts: x, W_down, W_unify, toqueries, tokeys, tovalues
    const int n0 = BT * EMB / 4, n1 = EMB * EMB / 4, n2 = EMB * EMB / 4;
    const int nw = NH * HD * HD / 4;
    convert6_kernel<<<(n0 + n1 + n2 + 3 * nw + 255) / 256, 256>>>(
        x, p_x16, n0, W_down, p_wd16, n1, W_unify, p_wu16, n2,
        toquery, p_wq16, nw, tokeys, p_wk16, nw, tovalues, p_wv16, nw);

    // 1) xd = x @ W_down   (fp16 HMMA, 64x64 warp tiles, fp16 output)
    hgemm_kernel<<<dim3(EMB / 128, BT / 128), 128, HG_SMEM>>>(
        p_x16, p_wd16, nullptr, nullptr, p_xd16);

    // 2) q,k,v per-head projections (all-fp16; q pre-scaled by log2e)
    qkv_mma_kernel<<<dim3(BATCH * NH, T_LEN / 128), 256>>>(
        p_xd16, p_wq16, p_wk16, p_wv16, p_q, p_k, p_v);

    // 3) flash attention (R15 best 2-stage variant) -> fp16 ao
    flash_mma_kernel<<<dim3(BATCH * NH, T_LEN / QT), 256, FLASH_SMEM>>>(
        p_q, p_k, p_v, p_ao16);

    // 4) out = ao @ W_unify + b_unify   (fp16 HMMA, 64x64 warp tiles, fp32 out)
    hgemm_kernel<<<dim3(EMB / 128, BT / 128), 128, HG_SMEM>>>(
        p_ao16, p_wu16, b_unify, out, nullptr);
}